// round 9
// baseline (speedup 1.0000x reference)
#include <cuda_runtime.h>
#include <cuda_fp16.h>
#include <cstdint>

#define D    128
#define NMAX 50000
#define EMAX 800000
#define NBMAX 64   // ceil(NMAX/1024)=49

// ---------------- scratch (device globals: allocation-free) ----------------
__device__ __align__(16) __half g_Ah[(size_t)NMAX * D];   // h_lin / hm (fp16, unscaled)
__device__ __align__(16) __half g_Bh[(size_t)NMAX * D];   // h post-relu (fp16)
__device__ __align__(16) float  g_Wcat[D * D];            // [w_mu | w_ls]
__device__ int   g_degi[NMAX];
__device__ float g_dis[NMAX];
__device__ int   g_off[NMAX];
__device__ int   g_cur[NMAX];
__device__ int   g_bsum[NBMAX];
__device__ __align__(16) int2 g_edge[EMAX];   // (src, dis[src] bits), CSR order
__device__ int   g_is32;

// ---------------- init: zero degrees + dtype detect + Wcat concat ----------------
__global__ void k_init(const long long* __restrict__ ei, int E, int n,
                       const float* __restrict__ wmu, const float* __restrict__ wls) {
    int i = blockIdx.x * blockDim.x + threadIdx.x;
    if (i < n) g_degi[i] = 0;
    if (i < D * D) {
        int k = i >> 7, c = i & 127;
        g_Wcat[i] = (c < 64) ? wmu[k * 64 + c] : wls[k * 64 + (c - 64)];
    }
    if (blockIdx.x == 0) {
        __shared__ int bad;
        if (threadIdx.x == 0) bad = 0;
        __syncthreads();
        int lim = E < 1024 ? E : 1024;
        for (int k = threadIdx.x; k < lim; k += blockDim.x) {
            long long v = ei[k];
            if (v < 0 || v >= (long long)n) bad = 1;
        }
        __syncthreads();
        if (threadIdx.x == 0) g_is32 = bad;
    }
}

// ---------------- fp16 MMA helper ----------------
__device__ __forceinline__ void mma_f16(float* c, const uint32_t* a,
                                        uint32_t b0, uint32_t b1) {
    asm volatile(
        "mma.sync.aligned.m16n8k16.row.col.f32.f16.f16.f32 "
        "{%0,%1,%2,%3}, {%4,%5,%6,%7}, {%8,%9}, {%0,%1,%2,%3};"
        : "+f"(c[0]), "+f"(c[1]), "+f"(c[2]), "+f"(c[3])
        : "r"(a[0]), "r"(a[1]), "r"(a[2]), "r"(a[3]), "r"(b0), "r"(b1));
}

// ---------------- GEMM body (unscaled output): OUT = X @ W, fp16 out ----------
// PASSES==2: X fp16 (exact A). PASSES==3: X fp32 split into fp16 hi+lo.
template <int PASSES, typename IT>
__device__ __forceinline__ void gemm_body(int bid, const IT* __restrict__ X,
                                          const float* __restrict__ W,
                                          __half* __restrict__ OUT, int nrows) {
    __shared__ __half2 Bs[2][128][9];
    __shared__ __half2 As[(PASSES == 3) ? 2 : 1][128][9];

    int tx = threadIdx.x;
    int lane = tx & 31, wp = tx >> 5;
    int g = lane >> 2, t = lane & 3;
    int rowBase = bid * 128;
    int wr = wp * 16;

    float c[16][4];
#pragma unroll
    for (int j = 0; j < 16; j++) {
        c[j][0] = 0.f; c[j][1] = 0.f; c[j][2] = 0.f; c[j][3] = 0.f;
    }

    for (int kc = 0; kc < 8; kc++) {
        int k0 = kc * 16;
#pragma unroll
        for (int it = 0; it < 4; it++) {
            int q = tx + it * 256;
            int n = q & 127, kp = q >> 7;
            float w0 = W[(size_t)(k0 + 2 * kp) * 128 + n];
            float w1 = W[(size_t)(k0 + 2 * kp + 1) * 128 + n];
            __half h0 = __float2half_rn(w0), h1 = __float2half_rn(w1);
            Bs[0][n][kp] = __halves2half2(h0, h1);
            Bs[1][n][kp] = __halves2half2(
                __float2half_rn(w0 - __half2float(h0)),
                __float2half_rn(w1 - __half2float(h1)));
        }
#pragma unroll
        for (int it = 0; it < 2; it++) {
            int q = tx + it * 256;
            int row = q >> 2, j4 = q & 3;
            int grow = rowBase + row;
            if (PASSES == 2) {
                uint2 u = (grow < nrows)
                          ? ((const uint2*)((const __half*)X + (size_t)grow * 128 + k0))[j4]
                          : make_uint2(0u, 0u);
                As[0][row][j4 * 2 + 0] = *(__half2*)&u.x;
                As[0][row][j4 * 2 + 1] = *(__half2*)&u.y;
            } else {
                float4 v = (grow < nrows)
                           ? ((const float4*)((const float*)X + (size_t)grow * 128 + k0))[j4]
                           : make_float4(0.f, 0.f, 0.f, 0.f);
                __half hx = __float2half_rn(v.x), hy = __float2half_rn(v.y);
                __half hz = __float2half_rn(v.z), hw = __float2half_rn(v.w);
                As[0][row][j4 * 2 + 0] = __halves2half2(hx, hy);
                As[0][row][j4 * 2 + 1] = __halves2half2(hz, hw);
                As[PASSES == 3 ? 1 : 0][row][j4 * 2 + 0] = __halves2half2(
                    __float2half_rn(v.x - __half2float(hx)),
                    __float2half_rn(v.y - __half2float(hy)));
                As[PASSES == 3 ? 1 : 0][row][j4 * 2 + 1] = __halves2half2(
                    __float2half_rn(v.z - __half2float(hz)),
                    __float2half_rn(v.w - __half2float(hw)));
            }
        }
        __syncthreads();

        uint32_t A0[4], A1[4];
        A0[0] = *(uint32_t*)&As[0][wr + g][t];
        A0[1] = *(uint32_t*)&As[0][wr + g + 8][t];
        A0[2] = *(uint32_t*)&As[0][wr + g][t + 4];
        A0[3] = *(uint32_t*)&As[0][wr + g + 8][t + 4];
        if (PASSES == 3) {
            A1[0] = *(uint32_t*)&As[1][wr + g][t];
            A1[1] = *(uint32_t*)&As[1][wr + g + 8][t];
            A1[2] = *(uint32_t*)&As[1][wr + g][t + 4];
            A1[3] = *(uint32_t*)&As[1][wr + g + 8][t + 4];
        }
#pragma unroll
        for (int j = 0; j < 16; j++) {
            uint32_t bh0 = *(uint32_t*)&Bs[0][j * 8 + g][t];
            uint32_t bh1 = *(uint32_t*)&Bs[0][j * 8 + g][t + 4];
            uint32_t bl0 = *(uint32_t*)&Bs[1][j * 8 + g][t];
            uint32_t bl1 = *(uint32_t*)&Bs[1][j * 8 + g][t + 4];
            mma_f16(c[j], A0, bh0, bh1);                   // Xh * Wh
            if (PASSES == 3) mma_f16(c[j], A1, bh0, bh1);  // Xl * Wh
            mma_f16(c[j], A0, bl0, bl1);                   // Xh * Wl
        }
        __syncthreads();
    }

    int r0 = rowBase + wr + g;
    int r1 = r0 + 8;
#pragma unroll
    for (int j = 0; j < 16; j++) {
        int col = j * 8 + 2 * t;
        if (r0 < nrows)
            *(__half2*)(OUT + (size_t)r0 * 128 + col) = __floats2half2_rn(c[j][0], c[j][1]);
        if (r1 < nrows)
            *(__half2*)(OUT + (size_t)r1 * 128 + col) = __floats2half2_rn(c[j][2], c[j][3]);
    }
}

// ---------------- fused: degree histogram (grid-stride) || GEMM1 ----------------
__global__ void __launch_bounds__(256, 2)
k_deg_gemm1(const void* __restrict__ ei, int E, int degBlocks,
            const float* __restrict__ X, const float* __restrict__ W,
            __half* __restrict__ OUT, int nrows) {
    if (blockIdx.x < degBlocks) {
        int stride = degBlocks * 256;
        for (int i = blockIdx.x * 256 + threadIdx.x; i < E; i += stride) {
            int d = g_is32 ? ((const int*)ei)[E + i]
                           : (int)((const long long*)ei)[(size_t)E + i];
            atomicAdd(&g_degi[d], 1);
        }
        return;
    }
    gemm_body<3, float>(blockIdx.x - degBlocks, X, W, OUT, nrows);
}

// plain GEMM2 wrapper
__global__ void __launch_bounds__(256, 2)
k_gemm2(const __half* __restrict__ X, const float* __restrict__ W,
        __half* __restrict__ OUT, int nrows) {
    gemm_body<2, __half>(blockIdx.x, X, W, OUT, nrows);
}

// ---- scan stage 1: per-block (1024) exclusive scan via warp shuffles + dis ----
__global__ void k_scan_local(int n) {
    __shared__ int ws[32];
    int t = threadIdx.x;
    int lane = t & 31, warp = t >> 5;
    int i = blockIdx.x * 1024 + t;
    int d = (i < n) ? g_degi[i] : 0;
    int v = d;
#pragma unroll
    for (int o = 1; o < 32; o <<= 1) {
        int u = __shfl_up_sync(0xFFFFFFFF, v, o);
        if (lane >= o) v += u;
    }
    if (lane == 31) ws[warp] = v;
    __syncthreads();
    if (warp == 0) {
        int s = ws[lane];
#pragma unroll
        for (int o = 1; o < 32; o <<= 1) {
            int u = __shfl_up_sync(0xFFFFFFFF, s, o);
            if (lane >= o) s += u;
        }
        ws[lane] = s;
    }
    __syncthreads();
    int incl = v + ((warp > 0) ? ws[warp - 1] : 0);
    if (i < n) {
        g_off[i] = incl - d;
        g_dis[i] = (d > 0) ? rsqrtf((float)d) : 0.0f;
    }
    if (t == 1023) g_bsum[blockIdx.x] = incl;
}

// ---- scan stage 2: inline bsum prefix + materialize off/cur ----
__global__ void k_scan_add(int n, int nb) {
    __shared__ int bs[NBMAX];
    int t = threadIdx.x;
    if (t < NBMAX) bs[t] = (t < nb) ? g_bsum[t] : 0;
    __syncthreads();
#pragma unroll
    for (int o = 1; o < NBMAX; o <<= 1) {
        int v = 0;
        if (t < NBMAX && t >= o) v = bs[t - o];
        __syncthreads();
        if (t < NBMAX) bs[t] += v;
        __syncthreads();
    }
    int i = blockIdx.x * blockDim.x + t;
    if (i < n) {
        int b = i >> 10;
        int o = g_off[i] + ((b > 0) ? bs[b - 1] : 0);
        g_off[i] = o;
        g_cur[i] = o;
    }
}

// decode (src,dst), place (src, dis[src]) at CSR cursor
__global__ void k_fill(const void* __restrict__ ei, int E) {
    int i = blockIdx.x * blockDim.x + threadIdx.x;
    if (i < E) {
        int s, d;
        if (g_is32) {
            const int* p = (const int*)ei;
            s = p[i]; d = p[E + i];
        } else {
            const long long* p = (const long long*)ei;
            s = (int)p[i]; d = (int)p[(size_t)E + i];
        }
        int pos = atomicAdd(&g_cur[d], 1);
        g_edge[pos] = make_int2(s, __float_as_int(g_dis[s]));
    }
}

// ---------------- warp-per-node gathers (edges carry dis[src]) ----------------
// Layer 1: h = relu(dis[w] * sum(dis[s]*h_lin[s]) + b1), fp16 in/out.
__global__ void k_gather_relu(const __half* __restrict__ h, __half* __restrict__ out,
                              const float* __restrict__ b1, int n) {
    int w = (blockIdx.x * blockDim.x + threadIdx.x) >> 5;
    int lane = threadIdx.x & 31;
    if (w >= n) return;
    int start = g_off[w], deg = g_degi[w];
    float4 acc = make_float4(0.f, 0.f, 0.f, 0.f);
#pragma unroll 4
    for (int i = 0; i < deg; i++) {
        int2 ed = __ldg(&g_edge[start + i]);
        float ds = __int_as_float(ed.y);
        uint2 u = ((const uint2*)(h + (size_t)ed.x * 128))[lane];
        float2 v0 = __half22float2(*(__half2*)&u.x);
        float2 v1 = __half22float2(*(__half2*)&u.y);
        acc.x += ds * v0.x; acc.y += ds * v0.y;
        acc.z += ds * v1.x; acc.w += ds * v1.y;
    }
    float dw = g_dis[w];
    float4 b = ((const float4*)b1)[lane];
    acc.x = fmaxf(acc.x * dw + b.x, 0.f);
    acc.y = fmaxf(acc.y * dw + b.y, 0.f);
    acc.z = fmaxf(acc.z * dw + b.z, 0.f);
    acc.w = fmaxf(acc.w * dw + b.w, 0.f);
    uint2 o;
    *(__half2*)&o.x = __floats2half2_rn(acc.x, acc.y);
    *(__half2*)&o.y = __floats2half2_rn(acc.z, acc.w);
    ((uint2*)(out + (size_t)w * 128))[lane] = o;
}

// Layer 2: fp16 hm in, fp32 split mu|logstd out with fused bias.
__global__ void k_gather_out(const __half* __restrict__ h, float* __restrict__ out,
                             const float* __restrict__ bmu, const float* __restrict__ bls,
                             int half, int n) {
    int w = (blockIdx.x * blockDim.x + threadIdx.x) >> 5;
    int lane = threadIdx.x & 31;
    if (w >= n) return;
    int start = g_off[w], deg = g_degi[w];
    float4 acc = make_float4(0.f, 0.f, 0.f, 0.f);
#pragma unroll 4
    for (int i = 0; i < deg; i++) {
        int2 ed = __ldg(&g_edge[start + i]);
        float ds = __int_as_float(ed.y);
        uint2 u = ((const uint2*)(h + (size_t)ed.x * 128))[lane];
        float2 v0 = __half22float2(*(__half2*)&u.x);
        float2 v1 = __half22float2(*(__half2*)&u.y);
        acc.x += ds * v0.x; acc.y += ds * v0.y;
        acc.z += ds * v1.x; acc.w += ds * v1.y;
    }
    float dw = g_dis[w];
    int col = lane * 4;
    float4 b; float* p;
    if (col < 64) {
        b = ((const float4*)bmu)[lane];
        p = out + (size_t)w * 64 + col;
    } else {
        b = ((const float4*)bls)[lane - 16];
        p = out + half + (size_t)w * 64 + (col - 64);
    }
    acc.x = acc.x * dw + b.x; acc.y = acc.y * dw + b.y;
    acc.z = acc.z * dw + b.z; acc.w = acc.w * dw + b.w;
    *(float4*)p = acc;
}

// ---------------- launch ----------------
extern "C" void kernel_launch(void* const* d_in, const int* in_sizes, int n_in,
                              void* d_out, int out_size) {
    const float* x   = (const float*)d_in[0];
    const void*  ei  = d_in[1];
    const float* w1  = (const float*)d_in[2];
    const float* b1  = (const float*)d_in[3];
    const float* wmu = (const float*)d_in[4];
    const float* bmu = (const float*)d_in[5];
    const float* wls = (const float*)d_in[6];
    const float* bls = (const float*)d_in[7];
    float* out = (float*)d_out;

    int n = in_sizes[0] / D;          // 50000
    int E = in_sizes[1] / 2;          // 800000
    int half = out_size / 2;          // n*64

    __half *Ah, *Bh;
    float *Wc;
    cudaGetSymbolAddress((void**)&Ah, g_Ah);
    cudaGetSymbolAddress((void**)&Bh, g_Bh);
    cudaGetSymbolAddress((void**)&Wc, g_Wcat);

    const int T = 256;
    int nb = (n + 1023) / 1024;
    int gemmBlocks = (n + 127) / 128;
    int degBlocks = 256;
    int gatherBlocks = (n * 32 + T - 1) / T;

    // init (deg zero + detect + Wcat)
    k_init<<<(n + T - 1) / T, T>>>((const long long*)ei, E, n, wmu, wls);
    // degree histogram || GEMM1 (h_lin = x @ w1, unscaled fp16)
    k_deg_gemm1<<<degBlocks + gemmBlocks, T>>>(ei, E, degBlocks, x, w1, Ah, n);
    // CSR offsets
    k_scan_local<<<nb, 1024>>>(n);
    k_scan_add<<<(n + T - 1) / T, T>>>(n, nb);
    k_fill<<<(E + T - 1) / T, T>>>(ei, E);
    // layer 1 aggregate
    k_gather_relu<<<gatherBlocks, T>>>(Ah, Bh, b1, n);
    // layer 2: hm = h @ [w_mu|w_ls] (unscaled) ; aggregate into split output
    k_gemm2<<<gemmBlocks, T>>>(Bh, Wc, Ah, n);
    k_gather_out<<<gatherBlocks, T>>>(Ah, out, bmu, bls, half, n);
}

// round 10
// speedup vs baseline: 1.0770x; 1.0770x over previous
#include <cuda_runtime.h>
#include <cuda_fp16.h>
#include <cstdint>

#define D    128
#define NMAX 50000
#define EMAX 800000
#define NBMAX 64   // ceil(NMAX/1024)=49

// ---------------- scratch (device globals: allocation-free) ----------------
__device__ __align__(16) __half g_Ah[(size_t)NMAX * D];   // h_lin' / hm' (fp16, dis-scaled)
__device__ __align__(16) __half g_Bh[(size_t)NMAX * D];   // h post-relu (fp16)
__device__ __align__(16) float  g_Wcat[D * D];            // [w_mu | w_ls]
__device__ int   g_degi[NMAX];
__device__ float g_dis[NMAX];
__device__ int   g_off[NMAX];
__device__ int   g_cur[NMAX];
__device__ int   g_bsum[NBMAX];
__device__ int   g_eidx[EMAX];    // CSR-ordered src indices (norm factored out)
__device__ int   g_is32;

// ---------------- init: zero degrees + dtype detect + Wcat concat ----------------
__global__ void k_init(const long long* __restrict__ ei, int E, int n,
                       const float* __restrict__ wmu, const float* __restrict__ wls) {
    int i = blockIdx.x * blockDim.x + threadIdx.x;
    if (i < n) g_degi[i] = 0;
    if (i < D * D) {
        int k = i >> 7, c = i & 127;
        g_Wcat[i] = (c < 64) ? wmu[k * 64 + c] : wls[k * 64 + (c - 64)];
    }
    if (blockIdx.x == 0) {
        __shared__ int bad;
        if (threadIdx.x == 0) bad = 0;
        __syncthreads();
        int lim = E < 1024 ? E : 1024;
        for (int k = threadIdx.x; k < lim; k += blockDim.x) {
            long long v = ei[k];
            if (v < 0 || v >= (long long)n) bad = 1;
        }
        __syncthreads();
        if (threadIdx.x == 0) g_is32 = bad;
    }
}

// decode dst straight from edge_index, histogram degrees
__global__ void k_deg(const void* __restrict__ ei, int E) {
    int i = blockIdx.x * blockDim.x + threadIdx.x;
    if (i < E) {
        int d = g_is32 ? ((const int*)ei)[E + i]
                       : (int)((const long long*)ei)[(size_t)E + i];
        atomicAdd(&g_degi[d], 1);
    }
}

// ---- scan stage 1: per-block (1024) exclusive scan via warp shuffles + dis ----
__global__ void k_scan_local(int n) {
    __shared__ int ws[32];
    int t = threadIdx.x;
    int lane = t & 31, warp = t >> 5;
    int i = blockIdx.x * 1024 + t;
    int d = (i < n) ? g_degi[i] : 0;
    int v = d;
#pragma unroll
    for (int o = 1; o < 32; o <<= 1) {
        int u = __shfl_up_sync(0xFFFFFFFF, v, o);
        if (lane >= o) v += u;
    }
    if (lane == 31) ws[warp] = v;
    __syncthreads();
    if (warp == 0) {
        int s = ws[lane];
#pragma unroll
        for (int o = 1; o < 32; o <<= 1) {
            int u = __shfl_up_sync(0xFFFFFFFF, s, o);
            if (lane >= o) s += u;
        }
        ws[lane] = s;
    }
    __syncthreads();
    int incl = v + ((warp > 0) ? ws[warp - 1] : 0);
    if (i < n) {
        g_off[i] = incl - d;
        g_dis[i] = (d > 0) ? rsqrtf((float)d) : 0.0f;
    }
    if (t == 1023) g_bsum[blockIdx.x] = incl;
}

// ---- scan stage 2: inline bsum prefix + materialize off/cur ----
__global__ void k_scan_add(int n, int nb) {
    __shared__ int bs[NBMAX];
    int t = threadIdx.x;
    if (t < NBMAX) bs[t] = (t < nb) ? g_bsum[t] : 0;
    __syncthreads();
#pragma unroll
    for (int o = 1; o < NBMAX; o <<= 1) {
        int v = 0;
        if (t < NBMAX && t >= o) v = bs[t - o];
        __syncthreads();
        if (t < NBMAX) bs[t] += v;
        __syncthreads();
    }
    int i = blockIdx.x * blockDim.x + t;
    if (i < n) {
        int b = i >> 10;
        int o = g_off[i] + ((b > 0) ? bs[b - 1] : 0);
        g_off[i] = o;
        g_cur[i] = o;
    }
}

// ---------------- fp16 MMA helper ----------------
__device__ __forceinline__ void mma_f16(float* c, const uint32_t* a,
                                        uint32_t b0, uint32_t b1) {
    asm volatile(
        "mma.sync.aligned.m16n8k16.row.col.f32.f16.f16.f32 "
        "{%0,%1,%2,%3}, {%4,%5,%6,%7}, {%8,%9}, {%0,%1,%2,%3};"
        : "+f"(c[0]), "+f"(c[1]), "+f"(c[2]), "+f"(c[3])
        : "r"(a[0]), "r"(a[1]), "r"(a[2]), "r"(a[3]), "r"(b0), "r"(b1));
}

// ---------------- GEMM body: OUT[r,:] = dis[r] * (X[r,:] @ W), fp16 out ------
// PASSES==2: X fp16 (exact A). PASSES==3: X fp32 split into fp16 hi+lo.
template <int PASSES, typename IT>
__device__ __forceinline__ void gemm_body(int bid, const IT* __restrict__ X,
                                          const float* __restrict__ W,
                                          __half* __restrict__ OUT, int nrows) {
    __shared__ __half2 Bs[2][128][9];
    __shared__ __half2 As[(PASSES == 3) ? 2 : 1][128][9];

    int tx = threadIdx.x;
    int lane = tx & 31, wp = tx >> 5;
    int g = lane >> 2, t = lane & 3;
    int rowBase = bid * 128;
    int wr = wp * 16;

    float c[16][4];
#pragma unroll
    for (int j = 0; j < 16; j++) {
        c[j][0] = 0.f; c[j][1] = 0.f; c[j][2] = 0.f; c[j][3] = 0.f;
    }

    for (int kc = 0; kc < 8; kc++) {
        int k0 = kc * 16;
#pragma unroll
        for (int it = 0; it < 4; it++) {
            int q = tx + it * 256;
            int n = q & 127, kp = q >> 7;
            float w0 = W[(size_t)(k0 + 2 * kp) * 128 + n];
            float w1 = W[(size_t)(k0 + 2 * kp + 1) * 128 + n];
            __half h0 = __float2half_rn(w0), h1 = __float2half_rn(w1);
            Bs[0][n][kp] = __halves2half2(h0, h1);
            Bs[1][n][kp] = __halves2half2(
                __float2half_rn(w0 - __half2float(h0)),
                __float2half_rn(w1 - __half2float(h1)));
        }
#pragma unroll
        for (int it = 0; it < 2; it++) {
            int q = tx + it * 256;
            int row = q >> 2, j4 = q & 3;
            int grow = rowBase + row;
            if (PASSES == 2) {
                uint2 u = (grow < nrows)
                          ? ((const uint2*)((const __half*)X + (size_t)grow * 128 + k0))[j4]
                          : make_uint2(0u, 0u);
                As[0][row][j4 * 2 + 0] = *(__half2*)&u.x;
                As[0][row][j4 * 2 + 1] = *(__half2*)&u.y;
            } else {
                float4 v = (grow < nrows)
                           ? ((const float4*)((const float*)X + (size_t)grow * 128 + k0))[j4]
                           : make_float4(0.f, 0.f, 0.f, 0.f);
                __half hx = __float2half_rn(v.x), hy = __float2half_rn(v.y);
                __half hz = __float2half_rn(v.z), hw = __float2half_rn(v.w);
                As[0][row][j4 * 2 + 0] = __halves2half2(hx, hy);
                As[0][row][j4 * 2 + 1] = __halves2half2(hz, hw);
                As[PASSES == 3 ? 1 : 0][row][j4 * 2 + 0] = __halves2half2(
                    __float2half_rn(v.x - __half2float(hx)),
                    __float2half_rn(v.y - __half2float(hy)));
                As[PASSES == 3 ? 1 : 0][row][j4 * 2 + 1] = __halves2half2(
                    __float2half_rn(v.z - __half2float(hz)),
                    __float2half_rn(v.w - __half2float(hw)));
            }
        }
        __syncthreads();

        uint32_t A0[4], A1[4];
        A0[0] = *(uint32_t*)&As[0][wr + g][t];
        A0[1] = *(uint32_t*)&As[0][wr + g + 8][t];
        A0[2] = *(uint32_t*)&As[0][wr + g][t + 4];
        A0[3] = *(uint32_t*)&As[0][wr + g + 8][t + 4];
        if (PASSES == 3) {
            A1[0] = *(uint32_t*)&As[1][wr + g][t];
            A1[1] = *(uint32_t*)&As[1][wr + g + 8][t];
            A1[2] = *(uint32_t*)&As[1][wr + g][t + 4];
            A1[3] = *(uint32_t*)&As[1][wr + g + 8][t + 4];
        }
#pragma unroll
        for (int j = 0; j < 16; j++) {
            uint32_t bh0 = *(uint32_t*)&Bs[0][j * 8 + g][t];
            uint32_t bh1 = *(uint32_t*)&Bs[0][j * 8 + g][t + 4];
            uint32_t bl0 = *(uint32_t*)&Bs[1][j * 8 + g][t];
            uint32_t bl1 = *(uint32_t*)&Bs[1][j * 8 + g][t + 4];
            mma_f16(c[j], A0, bh0, bh1);                   // Xh * Wh
            if (PASSES == 3) mma_f16(c[j], A1, bh0, bh1);  // Xl * Wh
            mma_f16(c[j], A0, bl0, bl1);                   // Xh * Wl
        }
        __syncthreads();
    }

    int r0 = rowBase + wr + g;
    int r1 = r0 + 8;
    float d0 = (r0 < nrows) ? g_dis[r0] : 0.f;
    float d1 = (r1 < nrows) ? g_dis[r1] : 0.f;
#pragma unroll
    for (int j = 0; j < 16; j++) {
        int col = j * 8 + 2 * t;
        if (r0 < nrows)
            *(__half2*)(OUT + (size_t)r0 * 128 + col) =
                __floats2half2_rn(c[j][0] * d0, c[j][1] * d0);
        if (r1 < nrows)
            *(__half2*)(OUT + (size_t)r1 * 128 + col) =
                __floats2half2_rn(c[j][2] * d1, c[j][3] * d1);
    }
}

// ---------------- fused: CSR fill || GEMM1, roles striped for co-residency ----
// Both need the scan done (fill: cursors; gemm1: dis epilogue), neither needs
// the other. Stripe roles across bid so the first wave holds both kinds.
__global__ void __launch_bounds__(256, 2)
k_fill_gemm1(const void* __restrict__ ei, int E, int fillBlocks,
             const float* __restrict__ X, const float* __restrict__ W,
             __half* __restrict__ OUT, int nrows) {
    int bid = blockIdx.x;
    bool isFill;
    int idx;
    if (bid < 2 * fillBlocks) {
        isFill = (bid & 1);
        idx = bid >> 1;
    } else {
        isFill = false;
        idx = fillBlocks + (bid - 2 * fillBlocks);
    }
    if (isFill) {
        int stride = fillBlocks * 256;
        for (int i = idx * 256 + threadIdx.x; i < E; i += stride) {
            int s, d;
            if (g_is32) {
                const int* p = (const int*)ei;
                s = p[i]; d = p[E + i];
            } else {
                const long long* p = (const long long*)ei;
                s = (int)p[i]; d = (int)p[(size_t)E + i];
            }
            int pos = atomicAdd(&g_cur[d], 1);
            g_eidx[pos] = s;
        }
        return;
    }
    gemm_body<3, float>(idx, X, W, OUT, nrows);
}

// plain GEMM2 wrapper
__global__ void __launch_bounds__(256, 2)
k_gemm2(const __half* __restrict__ X, const float* __restrict__ W,
        __half* __restrict__ OUT, int nrows) {
    gemm_body<2, __half>(blockIdx.x, X, W, OUT, nrows);
}

// ---------------- warp-per-node gathers (norm factored into gemm + node) -----
// Layer 1: h = relu(dis[w] * sum(h'[src]) + b1), fp16 in/out.
__global__ void k_gather_relu(const __half* __restrict__ h, __half* __restrict__ out,
                              const float* __restrict__ b1, int n) {
    int w = (blockIdx.x * blockDim.x + threadIdx.x) >> 5;
    int lane = threadIdx.x & 31;
    if (w >= n) return;
    int start = g_off[w], deg = g_degi[w];
    float4 acc = make_float4(0.f, 0.f, 0.f, 0.f);
#pragma unroll 4
    for (int i = 0; i < deg; i++) {
        int s = __ldg(&g_eidx[start + i]);
        uint2 u = ((const uint2*)(h + (size_t)s * 128))[lane];
        float2 v0 = __half22float2(*(__half2*)&u.x);
        float2 v1 = __half22float2(*(__half2*)&u.y);
        acc.x += v0.x; acc.y += v0.y;
        acc.z += v1.x; acc.w += v1.y;
    }
    float dw = g_dis[w];
    float4 b = ((const float4*)b1)[lane];
    acc.x = fmaxf(acc.x * dw + b.x, 0.f);
    acc.y = fmaxf(acc.y * dw + b.y, 0.f);
    acc.z = fmaxf(acc.z * dw + b.z, 0.f);
    acc.w = fmaxf(acc.w * dw + b.w, 0.f);
    uint2 o;
    *(__half2*)&o.x = __floats2half2_rn(acc.x, acc.y);
    *(__half2*)&o.y = __floats2half2_rn(acc.z, acc.w);
    ((uint2*)(out + (size_t)w * 128))[lane] = o;
}

// Layer 2: fp16 hm' in, fp32 split mu|logstd out with fused bias.
__global__ void k_gather_out(const __half* __restrict__ h, float* __restrict__ out,
                             const float* __restrict__ bmu, const float* __restrict__ bls,
                             int half, int n) {
    int w = (blockIdx.x * blockDim.x + threadIdx.x) >> 5;
    int lane = threadIdx.x & 31;
    if (w >= n) return;
    int start = g_off[w], deg = g_degi[w];
    float4 acc = make_float4(0.f, 0.f, 0.f, 0.f);
#pragma unroll 4
    for (int i = 0; i < deg; i++) {
        int s = __ldg(&g_eidx[start + i]);
        uint2 u = ((const uint2*)(h + (size_t)s * 128))[lane];
        float2 v0 = __half22float2(*(__half2*)&u.x);
        float2 v1 = __half22float2(*(__half2*)&u.y);
        acc.x += v0.x; acc.y += v0.y;
        acc.z += v1.x; acc.w += v1.y;
    }
    float dw = g_dis[w];
    int col = lane * 4;
    float4 b; float* p;
    if (col < 64) {
        b = ((const float4*)bmu)[lane];
        p = out + (size_t)w * 64 + col;
    } else {
        b = ((const float4*)bls)[lane - 16];
        p = out + half + (size_t)w * 64 + (col - 64);
    }
    acc.x = acc.x * dw + b.x; acc.y = acc.y * dw + b.y;
    acc.z = acc.z * dw + b.z; acc.w = acc.w * dw + b.w;
    *(float4*)p = acc;
}

// ---------------- launch ----------------
extern "C" void kernel_launch(void* const* d_in, const int* in_sizes, int n_in,
                              void* d_out, int out_size) {
    const float* x   = (const float*)d_in[0];
    const void*  ei  = d_in[1];
    const float* w1  = (const float*)d_in[2];
    const float* b1  = (const float*)d_in[3];
    const float* wmu = (const float*)d_in[4];
    const float* bmu = (const float*)d_in[5];
    const float* wls = (const float*)d_in[6];
    const float* bls = (const float*)d_in[7];
    float* out = (float*)d_out;

    int n = in_sizes[0] / D;          // 50000
    int E = in_sizes[1] / 2;          // 800000
    int half = out_size / 2;          // n*64

    __half *Ah, *Bh;
    float *Wc;
    cudaGetSymbolAddress((void**)&Ah, g_Ah);
    cudaGetSymbolAddress((void**)&Bh, g_Bh);
    cudaGetSymbolAddress((void**)&Wc, g_Wcat);

    const int T = 256;
    int nb = (n + 1023) / 1024;
    int gemmBlocks = (n + 127) / 128;
    int fillBlocks = 256;
    int gatherBlocks = (n * 32 + T - 1) / T;

    // CSR prefix + metadata
    k_init<<<(n + T - 1) / T, T>>>((const long long*)ei, E, n, wmu, wls);
    k_deg<<<(E + T - 1) / T, T>>>(ei, E);
    k_scan_local<<<nb, 1024>>>(n);
    k_scan_add<<<(n + T - 1) / T, T>>>(n, nb);
    // CSR fill || GEMM1 (h_lin' = dis .* (x @ w1)), striped roles
    k_fill_gemm1<<<fillBlocks + gemmBlocks, T>>>(ei, E, fillBlocks, x, w1, Ah, n);
    // layer 1 aggregate
    k_gather_relu<<<gatherBlocks, T>>>(Ah, Bh, b1, n);
    // layer 2: hm' = dis .* (h @ [w_mu|w_ls]) ; aggregate into split output
    k_gemm2<<<gemmBlocks, T>>>(Bh, Wc, Ah, n);
    k_gather_out<<<gatherBlocks, T>>>(Ah, out, bmu, bls, half, n);
}

// round 11
// speedup vs baseline: 1.0797x; 1.0024x over previous
#include <cuda_runtime.h>
#include <cuda_fp16.h>
#include <cstdint>

#define D    128
#define NMAX 50000
#define EMAX 800000
#define NBMAX 64   // ceil(NMAX/1024)=49
#define BFLAG 0x40000000

// ---------------- scratch (device globals: allocation-free) ----------------
__device__ __align__(16) __half g_Ah[(size_t)NMAX * D];   // h_lin' / hm' (fp16, dis-scaled)
__device__ __align__(16) __half g_Bh[(size_t)NMAX * D];   // h post-relu (fp16)
__device__ __align__(16) float  g_Wcat[D * D];            // [w_mu | w_ls]
__device__ int   g_degi[NMAX];    // zero at module load; re-zeroed by k_gather_out
__device__ float g_dis[NMAX];
__device__ int   g_off[NMAX];
__device__ int   g_cur[NMAX];
__device__ int   g_bsum[NBMAX];   // published block totals (value | BFLAG)
__device__ int   g_eidx[EMAX];    // CSR-ordered src indices (norm factored out)
__device__ int   g_is32;

// ------- init: Wcat concat + dtype detect + clear bsum flags (64 blocks) -------
__global__ void k_init(const long long* __restrict__ ei, int E, int n,
                       const float* __restrict__ wmu, const float* __restrict__ wls) {
    int i = blockIdx.x * blockDim.x + threadIdx.x;
    if (i < D * D) {
        int k = i >> 7, c = i & 127;
        g_Wcat[i] = (c < 64) ? wmu[k * 64 + c] : wls[k * 64 + (c - 64)];
    }
    if (blockIdx.x == 0) {
        if (threadIdx.x < NBMAX) g_bsum[threadIdx.x] = 0;
        __shared__ int bad;
        if (threadIdx.x == 0) bad = 0;
        __syncthreads();
        int lim = E < 1024 ? E : 1024;
        for (int k = threadIdx.x; k < lim; k += blockDim.x) {
            long long v = ei[k];
            if (v < 0 || v >= (long long)n) bad = 1;
        }
        __syncthreads();
        if (threadIdx.x == 0) g_is32 = bad;
    }
}

// decode dst straight from edge_index, histogram degrees
__global__ void k_deg(const void* __restrict__ ei, int E) {
    int i = blockIdx.x * blockDim.x + threadIdx.x;
    if (i < E) {
        int d = g_is32 ? ((const int*)ei)[E + i]
                       : (int)((const long long*)ei)[(size_t)E + i];
        atomicAdd(&g_degi[d], 1);
    }
}

// ---- single-kernel scan: local shuffle scan + cross-block lookback ----
// All nb (<=49) blocks are co-resident (148 SMs), so spinning is deadlock-free.
__global__ void k_scan(int n) {
    __shared__ int ws[32];
    __shared__ int stot;
    __shared__ int spre;
    int t = threadIdx.x;
    int lane = t & 31, warp = t >> 5;
    int i = blockIdx.x * 1024 + t;
    int d = (i < n) ? g_degi[i] : 0;
    int v = d;
#pragma unroll
    for (int o = 1; o < 32; o <<= 1) {
        int u = __shfl_up_sync(0xFFFFFFFF, v, o);
        if (lane >= o) v += u;
    }
    if (lane == 31) ws[warp] = v;
    if (t == 0) spre = 0;
    __syncthreads();
    if (warp == 0) {
        int s = ws[lane];
#pragma unroll
        for (int o = 1; o < 32; o <<= 1) {
            int u = __shfl_up_sync(0xFFFFFFFF, s, o);
            if (lane >= o) s += u;
        }
        ws[lane] = s;
    }
    __syncthreads();
    int incl = v + ((warp > 0) ? ws[warp - 1] : 0);
    if (t == 1023) stot = incl;
    __syncthreads();
    // publish own total (value and flag share one word -> no separate fence)
    if (t == 0) atomicExch(&g_bsum[blockIdx.x], stot | BFLAG);
    // lookback: thread t watches predecessor block t (nb <= 49 < 1024)
    if (t < blockIdx.x) {
        volatile int* vb = g_bsum;
        int pv;
        do { pv = vb[t]; } while (!(pv & BFLAG));
        atomicAdd(&spre, pv & ~BFLAG);
    }
    __syncthreads();
    if (i < n) {
        int o = spre + incl - d;
        g_off[i] = o;
        g_cur[i] = o;
        g_dis[i] = (d > 0) ? rsqrtf((float)d) : 0.0f;
    }
}

// ---------------- fp16 MMA helper ----------------
__device__ __forceinline__ void mma_f16(float* c, const uint32_t* a,
                                        uint32_t b0, uint32_t b1) {
    asm volatile(
        "mma.sync.aligned.m16n8k16.row.col.f32.f16.f16.f32 "
        "{%0,%1,%2,%3}, {%4,%5,%6,%7}, {%8,%9}, {%0,%1,%2,%3};"
        : "+f"(c[0]), "+f"(c[1]), "+f"(c[2]), "+f"(c[3])
        : "r"(a[0]), "r"(a[1]), "r"(a[2]), "r"(a[3]), "r"(b0), "r"(b1));
}

// ---------------- GEMM body: OUT[r,:] = dis[r] * (X[r,:] @ W), fp16 out ------
// PASSES==2: X fp16 (exact A). PASSES==3: X fp32 split into fp16 hi+lo.
template <int PASSES, typename IT>
__device__ __forceinline__ void gemm_body(int bid, const IT* __restrict__ X,
                                          const float* __restrict__ W,
                                          __half* __restrict__ OUT, int nrows) {
    __shared__ __half2 Bs[2][128][9];
    __shared__ __half2 As[(PASSES == 3) ? 2 : 1][128][9];

    int tx = threadIdx.x;
    int lane = tx & 31, wp = tx >> 5;
    int g = lane >> 2, t = lane & 3;
    int rowBase = bid * 128;
    int wr = wp * 16;

    float c[16][4];
#pragma unroll
    for (int j = 0; j < 16; j++) {
        c[j][0] = 0.f; c[j][1] = 0.f; c[j][2] = 0.f; c[j][3] = 0.f;
    }

    for (int kc = 0; kc < 8; kc++) {
        int k0 = kc * 16;
#pragma unroll
        for (int it = 0; it < 4; it++) {
            int q = tx + it * 256;
            int n = q & 127, kp = q >> 7;
            float w0 = W[(size_t)(k0 + 2 * kp) * 128 + n];
            float w1 = W[(size_t)(k0 + 2 * kp + 1) * 128 + n];
            __half h0 = __float2half_rn(w0), h1 = __float2half_rn(w1);
            Bs[0][n][kp] = __halves2half2(h0, h1);
            Bs[1][n][kp] = __halves2half2(
                __float2half_rn(w0 - __half2float(h0)),
                __float2half_rn(w1 - __half2float(h1)));
        }
#pragma unroll
        for (int it = 0; it < 2; it++) {
            int q = tx + it * 256;
            int row = q >> 2, j4 = q & 3;
            int grow = rowBase + row;
            if (PASSES == 2) {
                uint2 u = (grow < nrows)
                          ? ((const uint2*)((const __half*)X + (size_t)grow * 128 + k0))[j4]
                          : make_uint2(0u, 0u);
                As[0][row][j4 * 2 + 0] = *(__half2*)&u.x;
                As[0][row][j4 * 2 + 1] = *(__half2*)&u.y;
            } else {
                float4 v = (grow < nrows)
                           ? ((const float4*)((const float*)X + (size_t)grow * 128 + k0))[j4]
                           : make_float4(0.f, 0.f, 0.f, 0.f);
                __half hx = __float2half_rn(v.x), hy = __float2half_rn(v.y);
                __half hz = __float2half_rn(v.z), hw = __float2half_rn(v.w);
                As[0][row][j4 * 2 + 0] = __halves2half2(hx, hy);
                As[0][row][j4 * 2 + 1] = __halves2half2(hz, hw);
                As[PASSES == 3 ? 1 : 0][row][j4 * 2 + 0] = __halves2half2(
                    __float2half_rn(v.x - __half2float(hx)),
                    __float2half_rn(v.y - __half2float(hy)));
                As[PASSES == 3 ? 1 : 0][row][j4 * 2 + 1] = __halves2half2(
                    __float2half_rn(v.z - __half2float(hz)),
                    __float2half_rn(v.w - __half2float(hw)));
            }
        }
        __syncthreads();

        uint32_t A0[4], A1[4];
        A0[0] = *(uint32_t*)&As[0][wr + g][t];
        A0[1] = *(uint32_t*)&As[0][wr + g + 8][t];
        A0[2] = *(uint32_t*)&As[0][wr + g][t + 4];
        A0[3] = *(uint32_t*)&As[0][wr + g + 8][t + 4];
        if (PASSES == 3) {
            A1[0] = *(uint32_t*)&As[1][wr + g][t];
            A1[1] = *(uint32_t*)&As[1][wr + g + 8][t];
            A1[2] = *(uint32_t*)&As[1][wr + g][t + 4];
            A1[3] = *(uint32_t*)&As[1][wr + g + 8][t + 4];
        }
#pragma unroll
        for (int j = 0; j < 16; j++) {
            uint32_t bh0 = *(uint32_t*)&Bs[0][j * 8 + g][t];
            uint32_t bh1 = *(uint32_t*)&Bs[0][j * 8 + g][t + 4];
            uint32_t bl0 = *(uint32_t*)&Bs[1][j * 8 + g][t];
            uint32_t bl1 = *(uint32_t*)&Bs[1][j * 8 + g][t + 4];
            mma_f16(c[j], A0, bh0, bh1);                   // Xh * Wh
            if (PASSES == 3) mma_f16(c[j], A1, bh0, bh1);  // Xl * Wh
            mma_f16(c[j], A0, bl0, bl1);                   // Xh * Wl
        }
        __syncthreads();
    }

    int r0 = rowBase + wr + g;
    int r1 = r0 + 8;
    float d0 = (r0 < nrows) ? g_dis[r0] : 0.f;
    float d1 = (r1 < nrows) ? g_dis[r1] : 0.f;
#pragma unroll
    for (int j = 0; j < 16; j++) {
        int col = j * 8 + 2 * t;
        if (r0 < nrows)
            *(__half2*)(OUT + (size_t)r0 * 128 + col) =
                __floats2half2_rn(c[j][0] * d0, c[j][1] * d0);
        if (r1 < nrows)
            *(__half2*)(OUT + (size_t)r1 * 128 + col) =
                __floats2half2_rn(c[j][2] * d1, c[j][3] * d1);
    }
}

// ---------------- fused: CSR fill || GEMM1, roles striped for co-residency ----
__global__ void __launch_bounds__(256, 2)
k_fill_gemm1(const void* __restrict__ ei, int E, int fillBlocks,
             const float* __restrict__ X, const float* __restrict__ W,
             __half* __restrict__ OUT, int nrows) {
    int bid = blockIdx.x;
    bool isFill;
    int idx;
    if (bid < 2 * fillBlocks) {
        isFill = (bid & 1);
        idx = bid >> 1;
    } else {
        isFill = false;
        idx = fillBlocks + (bid - 2 * fillBlocks);
    }
    if (isFill) {
        int stride = fillBlocks * 256;
        for (int i = idx * 256 + threadIdx.x; i < E; i += stride) {
            int s, d;
            if (g_is32) {
                const int* p = (const int*)ei;
                s = p[i]; d = p[E + i];
            } else {
                const long long* p = (const long long*)ei;
                s = (int)p[i]; d = (int)p[(size_t)E + i];
            }
            int pos = atomicAdd(&g_cur[d], 1);
            g_eidx[pos] = s;
        }
        return;
    }
    gemm_body<3, float>(idx, X, W, OUT, nrows);
}

// plain GEMM2 wrapper
__global__ void __launch_bounds__(256, 2)
k_gemm2(const __half* __restrict__ X, const float* __restrict__ W,
        __half* __restrict__ OUT, int nrows) {
    gemm_body<2, __half>(blockIdx.x, X, W, OUT, nrows);
}

// ---------------- warp-per-node gathers (norm factored into gemm + node) -----
// Layer 1: h = relu(dis[w] * sum(h'[src]) + b1), fp16 in/out.
__global__ void k_gather_relu(const __half* __restrict__ h, __half* __restrict__ out,
                              const float* __restrict__ b1, int n) {
    int w = (blockIdx.x * blockDim.x + threadIdx.x) >> 5;
    int lane = threadIdx.x & 31;
    if (w >= n) return;
    int start = g_off[w], deg = g_degi[w];
    float4 acc = make_float4(0.f, 0.f, 0.f, 0.f);
#pragma unroll 4
    for (int i = 0; i < deg; i++) {
        int s = __ldg(&g_eidx[start + i]);
        uint2 u = ((const uint2*)(h + (size_t)s * 128))[lane];
        float2 v0 = __half22float2(*(__half2*)&u.x);
        float2 v1 = __half22float2(*(__half2*)&u.y);
        acc.x += v0.x; acc.y += v0.y;
        acc.z += v1.x; acc.w += v1.y;
    }
    float dw = g_dis[w];
    float4 b = ((const float4*)b1)[lane];
    acc.x = fmaxf(acc.x * dw + b.x, 0.f);
    acc.y = fmaxf(acc.y * dw + b.y, 0.f);
    acc.z = fmaxf(acc.z * dw + b.z, 0.f);
    acc.w = fmaxf(acc.w * dw + b.w, 0.f);
    uint2 o;
    *(__half2*)&o.x = __floats2half2_rn(acc.x, acc.y);
    *(__half2*)&o.y = __floats2half2_rn(acc.z, acc.w);
    ((uint2*)(out + (size_t)w * 128))[lane] = o;
}

// Layer 2: fp16 hm' in, fp32 split mu|logstd out with fused bias.
// Epilogue re-zeroes g_degi[w] for the next call (deterministic per call).
__global__ void k_gather_out(const __half* __restrict__ h, float* __restrict__ out,
                             const float* __restrict__ bmu, const float* __restrict__ bls,
                             int half, int n) {
    int w = (blockIdx.x * blockDim.x + threadIdx.x) >> 5;
    int lane = threadIdx.x & 31;
    if (w >= n) return;
    int start = g_off[w], deg = g_degi[w];
    float4 acc = make_float4(0.f, 0.f, 0.f, 0.f);
#pragma unroll 4
    for (int i = 0; i < deg; i++) {
        int s = __ldg(&g_eidx[start + i]);
        uint2 u = ((const uint2*)(h + (size_t)s * 128))[lane];
        float2 v0 = __half22float2(*(__half2*)&u.x);
        float2 v1 = __half22float2(*(__half2*)&u.y);
        acc.x += v0.x; acc.y += v0.y;
        acc.z += v1.x; acc.w += v1.y;
    }
    if (lane == 0) g_degi[w] = 0;   // reset for next launch
    float dw = g_dis[w];
    int col = lane * 4;
    float4 b; float* p;
    if (col < 64) {
        b = ((const float4*)bmu)[lane];
        p = out + (size_t)w * 64 + col;
    } else {
        b = ((const float4*)bls)[lane - 16];
        p = out + half + (size_t)w * 64 + (col - 64);
    }
    acc.x = acc.x * dw + b.x; acc.y = acc.y * dw + b.y;
    acc.z = acc.z * dw + b.z; acc.w = acc.w * dw + b.w;
    *(float4*)p = acc;
}

// ---------------- launch ----------------
extern "C" void kernel_launch(void* const* d_in, const int* in_sizes, int n_in,
                              void* d_out, int out_size) {
    const float* x   = (const float*)d_in[0];
    const void*  ei  = d_in[1];
    const float* w1  = (const float*)d_in[2];
    const float* b1  = (const float*)d_in[3];
    const float* wmu = (const float*)d_in[4];
    const float* bmu = (const float*)d_in[5];
    const float* wls = (const float*)d_in[6];
    const float* bls = (const float*)d_in[7];
    float* out = (float*)d_out;

    int n = in_sizes[0] / D;          // 50000
    int E = in_sizes[1] / 2;          // 800000
    int half = out_size / 2;          // n*64

    __half *Ah, *Bh;
    float *Wc;
    cudaGetSymbolAddress((void**)&Ah, g_Ah);
    cudaGetSymbolAddress((void**)&Bh, g_Bh);
    cudaGetSymbolAddress((void**)&Wc, g_Wcat);

    const int T = 256;
    int nb = (n + 1023) / 1024;       // 49 <= NBMAX, all co-resident
    int gemmBlocks = (n + 127) / 128;
    int fillBlocks = 256;
    int gatherBlocks = (n * 32 + T - 1) / T;

    // Wcat + dtype detect + bsum-flag clear
    k_init<<<(D * D + T - 1) / T, T>>>((const long long*)ei, E, n, wmu, wls);
    // degree histogram (degi pre-zeroed by previous call's k_gather_out)
    k_deg<<<(E + T - 1) / T, T>>>(ei, E);
    // fused exclusive scan (off/cur/dis) with cross-block lookback
    k_scan<<<nb, 1024>>>(n);
    // CSR fill || GEMM1 (h_lin' = dis .* (x @ w1)), striped roles
    k_fill_gemm1<<<fillBlocks + gemmBlocks, T>>>(ei, E, fillBlocks, x, w1, Ah, n);
    // layer 1 aggregate
    k_gather_relu<<<gatherBlocks, T>>>(Ah, Bh, b1, n);
    // layer 2: hm' = dis .* (h @ [w_mu|w_ls]) ; aggregate into split output
    k_gemm2<<<gemmBlocks, T>>>(Bh, Wc, Ah, n);
    k_gather_out<<<gatherBlocks, T>>>(Ah, out, bmu, bls, half, n);
}